// round 5
// baseline (speedup 1.0000x reference)
#include <cuda_runtime.h>
#include <cstdint>

// GCN 2-layer: h1 = relu(Anorm @ (x W1) + b1); out = log_softmax(Anorm @ (h1 W2) + b2)
// N=100000, E=1.6M, IN=256, HID=64, OUT=16.
// Inputs identified BY SIZE (robust to ordering):
//   x f32 [N,256] (25.6M), edge_index int32-or-int64 [2,E] (3.2M elems),
//   W1 [256,64] (16384), b1 [64], W2 [64,16] (1024), b2 [16].
// Output f32 [N,16].

#define MAX_N 100000
#define IN_K 256
#define HID 64
#define NOUT 16

__device__ __align__(16) float g_dinv[MAX_N];
__device__ __align__(16) float g_h1[(size_t)MAX_N * HID];
__device__ __align__(16) float g_agg1[(size_t)MAX_N * HID];
__device__ __align__(16) float g_h2[(size_t)MAX_N * NOUT];
__device__ int g_is64;

// ---------------- edge dtype detection ----------------
// int64 (little-endian, values < 2^31): every odd int32 word is 0.
// int32: odd words are node ids; 256 consecutive ids all being 0 has
// probability ~(1/N)^256 ~ 0. Two-sided check for robustness.
__global__ void k_detect(const int* __restrict__ ei) {
    if (threadIdx.x == 0 && blockIdx.x == 0) {
        int odd_or = 0;
        int in_range32 = 1;
#pragma unroll 8
        for (int i = 0; i < 256; ++i) {
            int lo = ei[2 * i];
            int hi = ei[2 * i + 1];
            odd_or |= hi;
            // if data were int32, both words are node ids in [0, 2^27)
            if (((unsigned)lo >= (1u << 27)) || ((unsigned)hi >= (1u << 27)))
                in_range32 = 0;
        }
        // odd words all zero -> int64; otherwise int32 (sanity: int32 ids in range)
        g_is64 = (odd_or == 0) ? 1 : 0;
        (void)in_range32;
    }
}

__device__ __forceinline__ int edge_at(const void* base, int is64, long long idx) {
    if (is64) return (int)((const long long*)base)[idx];
    return ((const int*)base)[idx];
}

// ---------------- degree / normalization ----------------
__global__ void k_deg_init(int n) {
    int i = blockIdx.x * blockDim.x + threadIdx.x;
    if (i < n) g_dinv[i] = 1.0f;  // self-loop
}

__global__ void k_deg_count(const void* __restrict__ ei, int E) {
    int i = blockIdx.x * blockDim.x + threadIdx.x;
    if (i >= E) return;
    int is64 = g_is64;
    int d = edge_at(ei, is64, (long long)E + i);   // dst row
    atomicAdd(&g_dinv[d], 1.0f);
}

__global__ void k_rsqrt(int n) {
    int i = blockIdx.x * blockDim.x + threadIdx.x;
    if (i < n) g_dinv[i] = rsqrtf(g_dinv[i]);
}

// ---------------- GEMM1: h1 = x @ W1  (N x 256) @ (256 x 64) ----------------
// Block tile: 128 rows x 64 cols, BK=16, 256 threads, 8x4 micro-tile per thread.
__global__ void k_gemm1(const float* __restrict__ X, const float* __restrict__ W, int N) {
    __shared__ __align__(16) float xs[16][132];  // [k][row], padded
    __shared__ __align__(16) float ws[16][64];   // [k][col]

    const int tid = threadIdx.x;
    const int tr = tid >> 4;        // 0..15  -> rows tr*8 .. tr*8+7
    const int tc = tid & 15;        // 0..15  -> cols tc*4 .. tc*4+3
    const int row0 = blockIdx.x * 128;

    float acc[8][4];
#pragma unroll
    for (int i = 0; i < 8; ++i)
#pragma unroll
        for (int j = 0; j < 4; ++j) acc[i][j] = 0.0f;

    for (int kk = 0; kk < IN_K; kk += 16) {
#pragma unroll
        for (int i = 0; i < 2; ++i) {
            int f = tid + i * 256;          // float4 index 0..511
            int r = f >> 2;                 // 0..127
            int kc = (f & 3) * 4;           // 0,4,8,12
            int gr = row0 + r;
            float4 v = make_float4(0.f, 0.f, 0.f, 0.f);
            if (gr < N)
                v = *reinterpret_cast<const float4*>(X + (size_t)gr * IN_K + kk + kc);
            xs[kc + 0][r] = v.x; xs[kc + 1][r] = v.y;
            xs[kc + 2][r] = v.z; xs[kc + 3][r] = v.w;
        }
        {
            int k = tid >> 4;
            int c = (tid & 15) * 4;
            *reinterpret_cast<float4*>(&ws[k][c]) =
                *reinterpret_cast<const float4*>(W + (size_t)(kk + k) * HID + c);
        }
        __syncthreads();

#pragma unroll
        for (int k = 0; k < 16; ++k) {
            float4 a0 = *reinterpret_cast<float4*>(&xs[k][tr * 8]);
            float4 a1 = *reinterpret_cast<float4*>(&xs[k][tr * 8 + 4]);
            float4 b  = *reinterpret_cast<float4*>(&ws[k][tc * 4]);
            float a[8] = {a0.x, a0.y, a0.z, a0.w, a1.x, a1.y, a1.z, a1.w};
            float bv[4] = {b.x, b.y, b.z, b.w};
#pragma unroll
            for (int i = 0; i < 8; ++i)
#pragma unroll
                for (int j = 0; j < 4; ++j)
                    acc[i][j] += a[i] * bv[j];
        }
        __syncthreads();
    }

#pragma unroll
    for (int i = 0; i < 8; ++i) {
        int gr = row0 + tr * 8 + i;
        if (gr < N) {
            float4 v = make_float4(acc[i][0], acc[i][1], acc[i][2], acc[i][3]);
            *reinterpret_cast<float4*>(&g_h1[(size_t)gr * HID + tc * 4]) = v;
        }
    }
}

// ---------------- self-loop init: agg1 = dinv^2 * h1 ----------------
__global__ void k_self1(int n) {
    int i = blockIdx.x * blockDim.x + threadIdx.x;     // float4 index
    if (i >= n * (HID / 4)) return;
    int node = i >> 4;                                  // 16 float4 per node
    float w = g_dinv[node]; w *= w;
    float4 v = reinterpret_cast<const float4*>(g_h1)[i];
    v.x *= w; v.y *= w; v.z *= w; v.w *= w;
    reinterpret_cast<float4*>(g_agg1)[i] = v;
}

// ---------------- scatter1: agg1[dst] += norm * h1[src], 16 thr/edge ----------------
__global__ void k_scatter1(const void* __restrict__ ei, int E) {
    long long t = (long long)blockIdx.x * blockDim.x + threadIdx.x;
    int e = (int)(t >> 4);
    if (e >= E) return;
    int c = ((int)t & 15) * 4;
    int is64 = g_is64;
    int s = edge_at(ei, is64, e);
    int d = edge_at(ei, is64, (long long)E + e);
    float w = g_dinv[s] * g_dinv[d];
    float4 v = *reinterpret_cast<const float4*>(&g_h1[(size_t)s * HID + c]);
    float* a = &g_agg1[(size_t)d * HID + c];
    atomicAdd(a + 0, v.x * w);
    atomicAdd(a + 1, v.y * w);
    atomicAdd(a + 2, v.z * w);
    atomicAdd(a + 3, v.w * w);
}

// ---------------- GEMM2 (fused relu(agg1+b1)): h2 = relu(agg1+b1) @ W2 ----------------
__global__ void k_gemm2(const float* __restrict__ W2, const float* __restrict__ b1, int N) {
    __shared__ __align__(16) float ws[64][16];
    __shared__ float bs[64];
    for (int i = threadIdx.x; i < 64 * 16; i += blockDim.x)
        ws[i >> 4][i & 15] = W2[i];
    if (threadIdx.x < 64) bs[threadIdx.x] = b1[threadIdx.x];
    __syncthreads();

    int r = blockIdx.x * blockDim.x + threadIdx.x;
    if (r >= N) return;

    float4 acc[4];
#pragma unroll
    for (int j = 0; j < 4; ++j) acc[j] = make_float4(0.f, 0.f, 0.f, 0.f);

    const float4* xr = reinterpret_cast<const float4*>(g_agg1 + (size_t)r * HID);
#pragma unroll
    for (int k4 = 0; k4 < 16; ++k4) {
        float4 a = xr[k4];
        float aa[4];
        aa[0] = fmaxf(a.x + bs[k4 * 4 + 0], 0.f);
        aa[1] = fmaxf(a.y + bs[k4 * 4 + 1], 0.f);
        aa[2] = fmaxf(a.z + bs[k4 * 4 + 2], 0.f);
        aa[3] = fmaxf(a.w + bs[k4 * 4 + 3], 0.f);
#pragma unroll
        for (int u = 0; u < 4; ++u) {
            const float4* wr = reinterpret_cast<const float4*>(&ws[k4 * 4 + u][0]);
#pragma unroll
            for (int j = 0; j < 4; ++j) {
                float4 w = wr[j];
                acc[j].x += aa[u] * w.x;
                acc[j].y += aa[u] * w.y;
                acc[j].z += aa[u] * w.z;
                acc[j].w += aa[u] * w.w;
            }
        }
    }
    float4* o = reinterpret_cast<float4*>(g_h2 + (size_t)r * NOUT);
#pragma unroll
    for (int j = 0; j < 4; ++j) o[j] = acc[j];
}

// ---------------- self-loop init layer 2: out = dinv^2 * h2 ----------------
__global__ void k_self2(float* __restrict__ out, int n) {
    int i = blockIdx.x * blockDim.x + threadIdx.x;      // float4 index
    if (i >= n * (NOUT / 4)) return;
    int node = i >> 2;                                   // 4 float4 per node
    float w = g_dinv[node]; w *= w;
    float4 v = reinterpret_cast<const float4*>(g_h2)[i];
    v.x *= w; v.y *= w; v.z *= w; v.w *= w;
    reinterpret_cast<float4*>(out)[i] = v;
}

// ---------------- scatter2: out[dst] += norm * h2[src], 4 thr/edge ----------------
__global__ void k_scatter2(const void* __restrict__ ei, float* __restrict__ out, int E) {
    long long t = (long long)blockIdx.x * blockDim.x + threadIdx.x;
    int e = (int)(t >> 2);
    if (e >= E) return;
    int c = ((int)t & 3) * 4;
    int is64 = g_is64;
    int s = edge_at(ei, is64, e);
    int d = edge_at(ei, is64, (long long)E + e);
    float w = g_dinv[s] * g_dinv[d];
    float4 v = *reinterpret_cast<const float4*>(&g_h2[(size_t)s * NOUT + c]);
    float* a = &out[(size_t)d * NOUT + c];
    atomicAdd(a + 0, v.x * w);
    atomicAdd(a + 1, v.y * w);
    atomicAdd(a + 2, v.z * w);
    atomicAdd(a + 3, v.w * w);
}

// ---------------- finalize: out = log_softmax(out + b2) ----------------
__global__ void k_final(float* __restrict__ out, const float* __restrict__ b2, int n) {
    int r = blockIdx.x * blockDim.x + threadIdx.x;
    if (r >= n) return;
    float v[16];
    float4* o = reinterpret_cast<float4*>(out + (size_t)r * NOUT);
#pragma unroll
    for (int j = 0; j < 4; ++j) {
        float4 t = o[j];
        v[j * 4 + 0] = t.x + b2[j * 4 + 0];
        v[j * 4 + 1] = t.y + b2[j * 4 + 1];
        v[j * 4 + 2] = t.z + b2[j * 4 + 2];
        v[j * 4 + 3] = t.w + b2[j * 4 + 3];
    }
    float mx = v[0];
#pragma unroll
    for (int j = 1; j < 16; ++j) mx = fmaxf(mx, v[j]);
    float s = 0.f;
#pragma unroll
    for (int j = 0; j < 16; ++j) s += __expf(v[j] - mx);
    float l = mx + __logf(s);
#pragma unroll
    for (int j = 0; j < 4; ++j) {
        float4 t;
        t.x = v[j * 4 + 0] - l; t.y = v[j * 4 + 1] - l;
        t.z = v[j * 4 + 2] - l; t.w = v[j * 4 + 3] - l;
        o[j] = t;
    }
}

extern "C" void kernel_launch(void* const* d_in, const int* in_sizes, int n_in,
                              void* d_out, int out_size) {
    // Identify inputs by element count (all distinct).
    const float* x  = nullptr;  const void* ei = nullptr;
    const float* W1 = nullptr;  const float* b1 = nullptr;
    const float* W2 = nullptr;  const float* b2 = nullptr;
    int n_x = 0, n_e = 0;
    for (int i = 0; i < n_in; ++i) {
        int s = in_sizes[i];
        if      (s == 16)            b2 = (const float*)d_in[i];
        else if (s == 64)            b1 = (const float*)d_in[i];
        else if (s == 1024)          W2 = (const float*)d_in[i];
        else if (s == 256 * 64)      W1 = (const float*)d_in[i];
        else if (s == 3200000)     { ei = d_in[i]; n_e = s; }
        else                       { x = (const float*)d_in[i]; n_x = s; }
    }
    const int N = n_x / IN_K;
    const int E = n_e / 2;
    float* out = (float*)d_out;

    k_detect   <<<1, 32>>>((const int*)ei);
    k_deg_init <<<(N + 255) / 256, 256>>>(N);
    k_deg_count<<<(E + 255) / 256, 256>>>(ei, E);
    k_rsqrt    <<<(N + 255) / 256, 256>>>(N);

    k_gemm1    <<<(N + 127) / 128, 256>>>(x, W1, N);
    k_self1    <<<(N * (HID / 4) + 255) / 256, 256>>>(N);
    {
        long long threads = (long long)E * 16;
        k_scatter1<<<(unsigned)((threads + 255) / 256), 256>>>(ei, E);
    }

    k_gemm2    <<<(N + 255) / 256, 256>>>(W2, b1, N);
    k_self2    <<<(N * (NOUT / 4) + 255) / 256, 256>>>(out, N);
    {
        long long threads = (long long)E * 4;
        k_scatter2<<<(unsigned)((threads + 255) / 256), 256>>>(ei, out, E);
    }

    k_final    <<<(N + 255) / 256, 256>>>(out, b2, N);
}

// round 6
// speedup vs baseline: 1.8508x; 1.8508x over previous
#include <cuda_runtime.h>
#include <cstdint>

// GCN 2-layer: h1 = relu(Anorm @ (x W1) + b1); out = log_softmax(Anorm @ (h1 W2) + b2)
// N=100000, E=1.6M, IN=256, HID=64, OUT=16.
// Inputs identified BY SIZE. edge_index dtype (int32 vs int64) auto-detected.
// Strategy: build dst-CSR per launch (counting sort), then GATHER per node
// (register accumulation, single store) instead of scatter atomics.

#define MAX_N 100000
#define MAX_E 1600000
#define IN_K 256
#define HID 64
#define NOUT 16
#define SCAN_BS 1024

__device__ __align__(16) float g_dinv[MAX_N];
__device__ __align__(16) float g_h1[(size_t)MAX_N * HID];
__device__ __align__(16) float g_agg1[(size_t)MAX_N * HID];
__device__ __align__(16) float g_h2[(size_t)MAX_N * NOUT];
__device__ int g_cnt[MAX_N];
__device__ int g_cursor[MAX_N];
__device__ int g_offsets[MAX_N + 1];
__device__ int g_partial[(MAX_N + SCAN_BS - 1) / SCAN_BS];
__device__ int g_csr_src[MAX_E];
__device__ int g_is64;

// ---------------- edge dtype detection ----------------
// int64 little-endian with values < 2^31: every odd int32 word is 0.
// int32: odd words are node ids; 256 of them all zero ~ impossible.
__global__ void k_detect(const int* __restrict__ ei) {
    if (threadIdx.x == 0 && blockIdx.x == 0) {
        int odd_or = 0;
#pragma unroll 8
        for (int i = 0; i < 256; ++i) odd_or |= ei[2 * i + 1];
        g_is64 = (odd_or == 0) ? 1 : 0;
    }
}

__device__ __forceinline__ int edge_at(const void* base, int is64, long long idx) {
    if (is64) return (int)((const long long*)base)[idx];
    return ((const int*)base)[idx];
}

// ---------------- CSR build ----------------
__global__ void k_zero_cnt(int n) {
    int i = blockIdx.x * blockDim.x + threadIdx.x;
    if (i < n) g_cnt[i] = 0;
}

__global__ void k_count(const void* __restrict__ ei, int E) {
    int i = blockIdx.x * blockDim.x + threadIdx.x;
    if (i >= E) return;
    int d = edge_at(ei, g_is64, (long long)E + i);
    atomicAdd(&g_cnt[d], 1);
}

// block-local exclusive scan (Hillis-Steele inclusive, subtract own)
__global__ void k_scan1(int n) {
    __shared__ int sh[SCAN_BS];
    int i = blockIdx.x * SCAN_BS + threadIdx.x;
    int v = (i < n) ? g_cnt[i] : 0;
    sh[threadIdx.x] = v;
    __syncthreads();
#pragma unroll
    for (int off = 1; off < SCAN_BS; off <<= 1) {
        int t = (threadIdx.x >= off) ? sh[threadIdx.x - off] : 0;
        __syncthreads();
        sh[threadIdx.x] += t;
        __syncthreads();
    }
    if (i < n) g_offsets[i] = sh[threadIdx.x] - v;
    if (threadIdx.x == SCAN_BS - 1) g_partial[blockIdx.x] = sh[SCAN_BS - 1];
}

__global__ void k_scan2(int nb, int n) {
    if (threadIdx.x == 0 && blockIdx.x == 0) {
        int run = 0;
        for (int b = 0; b < nb; ++b) {
            int t = g_partial[b];
            g_partial[b] = run;
            run += t;
        }
        g_offsets[n] = run;  // == E
    }
}

__global__ void k_scan3(int n) {
    int i = blockIdx.x * blockDim.x + threadIdx.x;
    if (i < n) {
        g_offsets[i] += g_partial[i >> 10];
        g_cursor[i] = 0;
    }
}

__global__ void k_rsqrt(int n) {
    int i = blockIdx.x * blockDim.x + threadIdx.x;
    if (i < n) g_dinv[i] = rsqrtf((float)(g_cnt[i] + 1));  // +1 self-loop
}

__global__ void k_fill(const void* __restrict__ ei, int E) {
    int e = blockIdx.x * blockDim.x + threadIdx.x;
    if (e >= E) return;
    int is64 = g_is64;
    int s = edge_at(ei, is64, e);
    int d = edge_at(ei, is64, (long long)E + e);
    int pos = atomicAdd(&g_cursor[d], 1);
    g_csr_src[g_offsets[d] + pos] = s;
}

// ---------------- GEMM1: h1 = x @ W1  (N x 256) @ (256 x 64) ----------------
__global__ void k_gemm1(const float* __restrict__ X, const float* __restrict__ W, int N) {
    __shared__ __align__(16) float xs[16][132];
    __shared__ __align__(16) float ws[16][64];

    const int tid = threadIdx.x;
    const int tr = tid >> 4;
    const int tc = tid & 15;
    const int row0 = blockIdx.x * 128;

    float acc[8][4];
#pragma unroll
    for (int i = 0; i < 8; ++i)
#pragma unroll
        for (int j = 0; j < 4; ++j) acc[i][j] = 0.0f;

    for (int kk = 0; kk < IN_K; kk += 16) {
#pragma unroll
        for (int i = 0; i < 2; ++i) {
            int f = tid + i * 256;
            int r = f >> 2;
            int kc = (f & 3) * 4;
            int gr = row0 + r;
            float4 v = make_float4(0.f, 0.f, 0.f, 0.f);
            if (gr < N)
                v = *reinterpret_cast<const float4*>(X + (size_t)gr * IN_K + kk + kc);
            xs[kc + 0][r] = v.x; xs[kc + 1][r] = v.y;
            xs[kc + 2][r] = v.z; xs[kc + 3][r] = v.w;
        }
        {
            int k = tid >> 4;
            int c = (tid & 15) * 4;
            *reinterpret_cast<float4*>(&ws[k][c]) =
                *reinterpret_cast<const float4*>(W + (size_t)(kk + k) * HID + c);
        }
        __syncthreads();

#pragma unroll
        for (int k = 0; k < 16; ++k) {
            float4 a0 = *reinterpret_cast<float4*>(&xs[k][tr * 8]);
            float4 a1 = *reinterpret_cast<float4*>(&xs[k][tr * 8 + 4]);
            float4 b  = *reinterpret_cast<float4*>(&ws[k][tc * 4]);
            float a[8] = {a0.x, a0.y, a0.z, a0.w, a1.x, a1.y, a1.z, a1.w};
            float bv[4] = {b.x, b.y, b.z, b.w};
#pragma unroll
            for (int i = 0; i < 8; ++i)
#pragma unroll
                for (int j = 0; j < 4; ++j)
                    acc[i][j] += a[i] * bv[j];
        }
        __syncthreads();
    }

#pragma unroll
    for (int i = 0; i < 8; ++i) {
        int gr = row0 + tr * 8 + i;
        if (gr < N) {
            float4 v = make_float4(acc[i][0], acc[i][1], acc[i][2], acc[i][3]);
            *reinterpret_cast<float4*>(&g_h1[(size_t)gr * HID + tc * 4]) = v;
        }
    }
}

// ---------------- gather1: agg1[d] = dinv[d]^2*h1[d] + sum_e dinv[s]dinv[d]*h1[s] ----
// 16 threads per node, each owns one float4 column slice (64 floats total).
__global__ void k_gather1(int N) {
    int t = blockIdx.x * blockDim.x + threadIdx.x;
    int node = t >> 4;
    if (node >= N) return;
    int c = (t & 15) * 4;

    float dd = g_dinv[node];
    const float4* selfrow = reinterpret_cast<const float4*>(&g_h1[(size_t)node * HID + c]);
    float4 acc = *selfrow;
    float w0 = dd * dd;
    acc.x *= w0; acc.y *= w0; acc.z *= w0; acc.w *= w0;

    int j   = g_offsets[node];
    int end = g_offsets[node + 1];

    for (; j + 1 < end; j += 2) {
        int s0 = g_csr_src[j];
        int s1 = g_csr_src[j + 1];
        float w_0 = g_dinv[s0] * dd;
        float w_1 = g_dinv[s1] * dd;
        float4 v0 = *reinterpret_cast<const float4*>(&g_h1[(size_t)s0 * HID + c]);
        float4 v1 = *reinterpret_cast<const float4*>(&g_h1[(size_t)s1 * HID + c]);
        acc.x += w_0 * v0.x + w_1 * v1.x;
        acc.y += w_0 * v0.y + w_1 * v1.y;
        acc.z += w_0 * v0.z + w_1 * v1.z;
        acc.w += w_0 * v0.w + w_1 * v1.w;
    }
    if (j < end) {
        int s = g_csr_src[j];
        float w = g_dinv[s] * dd;
        float4 v = *reinterpret_cast<const float4*>(&g_h1[(size_t)s * HID + c]);
        acc.x += w * v.x; acc.y += w * v.y;
        acc.z += w * v.z; acc.w += w * v.w;
    }
    *reinterpret_cast<float4*>(&g_agg1[(size_t)node * HID + c]) = acc;
}

// ---------------- GEMM2 (fused relu(agg1+b1)): h2 = relu(agg1+b1) @ W2 ----------------
__global__ void k_gemm2(const float* __restrict__ W2, const float* __restrict__ b1, int N) {
    __shared__ __align__(16) float ws[64][16];
    __shared__ float bs[64];
    for (int i = threadIdx.x; i < 64 * 16; i += blockDim.x)
        ws[i >> 4][i & 15] = W2[i];
    if (threadIdx.x < 64) bs[threadIdx.x] = b1[threadIdx.x];
    __syncthreads();

    int r = blockIdx.x * blockDim.x + threadIdx.x;
    if (r >= N) return;

    float4 acc[4];
#pragma unroll
    for (int j = 0; j < 4; ++j) acc[j] = make_float4(0.f, 0.f, 0.f, 0.f);

    const float4* xr = reinterpret_cast<const float4*>(g_agg1 + (size_t)r * HID);
#pragma unroll
    for (int k4 = 0; k4 < 16; ++k4) {
        float4 a = xr[k4];
        float aa[4];
        aa[0] = fmaxf(a.x + bs[k4 * 4 + 0], 0.f);
        aa[1] = fmaxf(a.y + bs[k4 * 4 + 1], 0.f);
        aa[2] = fmaxf(a.z + bs[k4 * 4 + 2], 0.f);
        aa[3] = fmaxf(a.w + bs[k4 * 4 + 3], 0.f);
#pragma unroll
        for (int u = 0; u < 4; ++u) {
            const float4* wr = reinterpret_cast<const float4*>(&ws[k4 * 4 + u][0]);
#pragma unroll
            for (int j = 0; j < 4; ++j) {
                float4 w = wr[j];
                acc[j].x += aa[u] * w.x;
                acc[j].y += aa[u] * w.y;
                acc[j].z += aa[u] * w.z;
                acc[j].w += aa[u] * w.w;
            }
        }
    }
    float4* o = reinterpret_cast<float4*>(g_h2 + (size_t)r * NOUT);
#pragma unroll
    for (int j = 0; j < 4; ++j) o[j] = acc[j];
}

// ---------------- gather2: out[d] = dinv^2*h2[d] + sum_e w*h2[s] (4 thr/node) ----
__global__ void k_gather2(float* __restrict__ out, int N) {
    int t = blockIdx.x * blockDim.x + threadIdx.x;
    int node = t >> 2;
    if (node >= N) return;
    int c = (t & 3) * 4;

    float dd = g_dinv[node];
    float4 acc = *reinterpret_cast<const float4*>(&g_h2[(size_t)node * NOUT + c]);
    float w0 = dd * dd;
    acc.x *= w0; acc.y *= w0; acc.z *= w0; acc.w *= w0;

    int j   = g_offsets[node];
    int end = g_offsets[node + 1];

    for (; j + 1 < end; j += 2) {
        int s0 = g_csr_src[j];
        int s1 = g_csr_src[j + 1];
        float w_0 = g_dinv[s0] * dd;
        float w_1 = g_dinv[s1] * dd;
        float4 v0 = *reinterpret_cast<const float4*>(&g_h2[(size_t)s0 * NOUT + c]);
        float4 v1 = *reinterpret_cast<const float4*>(&g_h2[(size_t)s1 * NOUT + c]);
        acc.x += w_0 * v0.x + w_1 * v1.x;
        acc.y += w_0 * v0.y + w_1 * v1.y;
        acc.z += w_0 * v0.z + w_1 * v1.z;
        acc.w += w_0 * v0.w + w_1 * v1.w;
    }
    if (j < end) {
        int s = g_csr_src[j];
        float w = g_dinv[s] * dd;
        float4 v = *reinterpret_cast<const float4*>(&g_h2[(size_t)s * NOUT + c]);
        acc.x += w * v.x; acc.y += w * v.y;
        acc.z += w * v.z; acc.w += w * v.w;
    }
    *reinterpret_cast<float4*>(&out[(size_t)node * NOUT + c]) = acc;
}

// ---------------- finalize: out = log_softmax(out + b2) ----------------
__global__ void k_final(float* __restrict__ out, const float* __restrict__ b2, int n) {
    int r = blockIdx.x * blockDim.x + threadIdx.x;
    if (r >= n) return;
    float v[16];
    float4* o = reinterpret_cast<float4*>(out + (size_t)r * NOUT);
#pragma unroll
    for (int j = 0; j < 4; ++j) {
        float4 t = o[j];
        v[j * 4 + 0] = t.x + b2[j * 4 + 0];
        v[j * 4 + 1] = t.y + b2[j * 4 + 1];
        v[j * 4 + 2] = t.z + b2[j * 4 + 2];
        v[j * 4 + 3] = t.w + b2[j * 4 + 3];
    }
    float mx = v[0];
#pragma unroll
    for (int j = 1; j < 16; ++j) mx = fmaxf(mx, v[j]);
    float s = 0.f;
#pragma unroll
    for (int j = 0; j < 16; ++j) s += __expf(v[j] - mx);
    float l = mx + __logf(s);
#pragma unroll
    for (int j = 0; j < 4; ++j) {
        float4 t;
        t.x = v[j * 4 + 0] - l; t.y = v[j * 4 + 1] - l;
        t.z = v[j * 4 + 2] - l; t.w = v[j * 4 + 3] - l;
        o[j] = t;
    }
}

extern "C" void kernel_launch(void* const* d_in, const int* in_sizes, int n_in,
                              void* d_out, int out_size) {
    const float* x  = nullptr;  const void* ei = nullptr;
    const float* W1 = nullptr;  const float* b1 = nullptr;
    const float* W2 = nullptr;  const float* b2 = nullptr;
    int n_x = 0, n_e = 0;
    for (int i = 0; i < n_in; ++i) {
        int s = in_sizes[i];
        if      (s == 16)            b2 = (const float*)d_in[i];
        else if (s == 64)            b1 = (const float*)d_in[i];
        else if (s == 1024)          W2 = (const float*)d_in[i];
        else if (s == 256 * 64)      W1 = (const float*)d_in[i];
        else if (s == 3200000)     { ei = d_in[i]; n_e = s; }
        else                       { x = (const float*)d_in[i]; n_x = s; }
    }
    const int N = n_x / IN_K;
    const int E = n_e / 2;
    float* out = (float*)d_out;
    const int NB = (N + SCAN_BS - 1) / SCAN_BS;

    k_detect  <<<1, 32>>>((const int*)ei);
    k_zero_cnt<<<(N + 255) / 256, 256>>>(N);
    k_count   <<<(E + 255) / 256, 256>>>(ei, E);
    k_scan1   <<<NB, SCAN_BS>>>(N);
    k_scan2   <<<1, 32>>>(NB, N);
    k_scan3   <<<(N + 255) / 256, 256>>>(N);
    k_rsqrt   <<<(N + 255) / 256, 256>>>(N);
    k_fill    <<<(E + 255) / 256, 256>>>(ei, E);

    k_gemm1   <<<(N + 127) / 128, 256>>>(x, W1, N);
    k_gather1 <<<(N * 16 + 255) / 256, 256>>>(N);

    k_gemm2   <<<(N + 255) / 256, 256>>>(W2, b1, N);
    k_gather2 <<<(N * 4 + 255) / 256, 256>>>(out, N);

    k_final   <<<(N + 255) / 256, 256>>>(out, b2, N);
}

// round 7
// speedup vs baseline: 1.9365x; 1.0463x over previous
#include <cuda_runtime.h>
#include <cstdint>

// GCN 2-layer: h1 = relu(Anorm @ (x W1) + b1); out = log_softmax(Anorm @ (h1 W2) + b2)
// N=100000, E=1.6M, IN=256, HID=64, OUT=16.
// CSR-gather formulation (no float atomics). GEMM1 uses packed f32x2 FMA.

#define MAX_N 100000
#define MAX_E 1600000
#define IN_K 256
#define HID 64
#define NOUT 16
#define SCAN_BS 1024

__device__ __align__(16) float g_dinv[MAX_N];
__device__ __align__(16) float g_h1[(size_t)MAX_N * HID];
__device__ __align__(16) float g_agg1[(size_t)MAX_N * HID];
__device__ __align__(16) float g_h2[(size_t)MAX_N * NOUT];
__device__ int g_cnt[MAX_N];
__device__ int g_cursor[MAX_N];
__device__ int g_offsets[MAX_N + 1];
__device__ int g_partial[(MAX_N + SCAN_BS - 1) / SCAN_BS];
__device__ int g_csr_src[MAX_E];
__device__ int g_is64;

// ---------------- packed f32x2 helpers (Blackwell) ----------------
__device__ __forceinline__ unsigned long long pk2(float lo, float hi) {
    unsigned long long r;
    asm("mov.b64 %0, {%1, %2};" : "=l"(r) : "f"(lo), "f"(hi));
    return r;
}
__device__ __forceinline__ unsigned long long fma2(unsigned long long a,
                                                   unsigned long long b,
                                                   unsigned long long c) {
    unsigned long long d;
    asm("fma.rn.f32x2 %0, %1, %2, %3;" : "=l"(d) : "l"(a), "l"(b), "l"(c));
    return d;
}
__device__ __forceinline__ void upk2(unsigned long long v, float& lo, float& hi) {
    asm("mov.b64 {%0, %1}, %2;" : "=f"(lo), "=f"(hi) : "l"(v));
}

// ---------------- prep: zero counters + edge dtype detect ----------------
__global__ void k_prep(const int* __restrict__ ei, int n) {
    int i = blockIdx.x * blockDim.x + threadIdx.x;
    if (i < n) g_cnt[i] = 0;
    if (i == 0) {
        int odd_or = 0;
#pragma unroll 8
        for (int k = 0; k < 256; ++k) odd_or |= ei[2 * k + 1];
        g_is64 = (odd_or == 0) ? 1 : 0;   // int64 little-endian -> high words all 0
    }
}

__device__ __forceinline__ int edge_at(const void* base, int is64, long long idx) {
    if (is64) return (int)((const long long*)base)[idx];
    return ((const int*)base)[idx];
}

// ---------------- CSR build ----------------
__global__ void k_count(const void* __restrict__ ei, int E) {
    int i = blockIdx.x * blockDim.x + threadIdx.x;
    if (i >= E) return;
    int d = edge_at(ei, g_is64, (long long)E + i);
    atomicAdd(&g_cnt[d], 1);
}

__global__ void k_scan1(int n) {
    __shared__ int sh[SCAN_BS];
    int i = blockIdx.x * SCAN_BS + threadIdx.x;
    int v = (i < n) ? g_cnt[i] : 0;
    sh[threadIdx.x] = v;
    __syncthreads();
#pragma unroll
    for (int off = 1; off < SCAN_BS; off <<= 1) {
        int t = (threadIdx.x >= off) ? sh[threadIdx.x - off] : 0;
        __syncthreads();
        sh[threadIdx.x] += t;
        __syncthreads();
    }
    if (i < n) g_offsets[i] = sh[threadIdx.x] - v;
    if (threadIdx.x == SCAN_BS - 1) g_partial[blockIdx.x] = sh[SCAN_BS - 1];
}

__global__ void k_scan2(int nb, int n) {
    if (threadIdx.x == 0 && blockIdx.x == 0) {
        int run = 0;
        for (int b = 0; b < nb; ++b) {
            int t = g_partial[b];
            g_partial[b] = run;
            run += t;
        }
        g_offsets[n] = run;  // == E
    }
}

// offsets += block prefix; cursor=0; dinv = rsqrt(deg+1)
__global__ void k_scan3r(int n) {
    int i = blockIdx.x * blockDim.x + threadIdx.x;
    if (i < n) {
        g_offsets[i] += g_partial[i >> 10];
        g_cursor[i] = 0;
        g_dinv[i] = rsqrtf((float)(g_cnt[i] + 1));
    }
}

__global__ void k_fill(const void* __restrict__ ei, int E) {
    int e = blockIdx.x * blockDim.x + threadIdx.x;
    if (e >= E) return;
    int is64 = g_is64;
    int s = edge_at(ei, is64, e);
    int d = edge_at(ei, is64, (long long)E + e);
    int pos = atomicAdd(&g_cursor[d], 1);
    g_csr_src[g_offsets[d] + pos] = s;
}

// ---------------- GEMM1: h1 = x @ W1  (N x 256)@(256 x 64), f32x2 FMA ----------------
// 128 rows x 64 cols per block, BK=16, 256 threads, 8x4 per thread (as 4 row-pairs x 4 cols).
__global__ void k_gemm1(const float* __restrict__ X, const float* __restrict__ W, int N) {
    __shared__ __align__(16) float xs[16][132];   // [k][row]
    __shared__ __align__(16) float ws[16][64];    // [k][col]

    const int tid = threadIdx.x;
    const int tr = tid >> 4;        // row group: rows tr*8 .. tr*8+7
    const int tc = tid & 15;        // col group: cols tc*4 .. tc*4+3
    const int row0 = blockIdx.x * 128;

    unsigned long long acc2[4][4];  // [row-pair p][col j]: (row 2p, row 2p+1)
#pragma unroll
    for (int p = 0; p < 4; ++p)
#pragma unroll
        for (int j = 0; j < 4; ++j) acc2[p][j] = 0ULL;

    for (int kk = 0; kk < IN_K; kk += 16) {
#pragma unroll
        for (int i = 0; i < 2; ++i) {
            int f = tid + i * 256;
            int r = f >> 2;
            int kc = (f & 3) * 4;
            int gr = row0 + r;
            float4 v = make_float4(0.f, 0.f, 0.f, 0.f);
            if (gr < N)
                v = *reinterpret_cast<const float4*>(X + (size_t)gr * IN_K + kk + kc);
            xs[kc + 0][r] = v.x; xs[kc + 1][r] = v.y;
            xs[kc + 2][r] = v.z; xs[kc + 3][r] = v.w;
        }
        {
            int k = tid >> 4;
            int c = (tid & 15) * 4;
            *reinterpret_cast<float4*>(&ws[k][c]) =
                *reinterpret_cast<const float4*>(W + (size_t)(kk + k) * HID + c);
        }
        __syncthreads();

#pragma unroll
        for (int k = 0; k < 16; ++k) {
            float4 a0 = *reinterpret_cast<float4*>(&xs[k][tr * 8]);
            float4 a1 = *reinterpret_cast<float4*>(&xs[k][tr * 8 + 4]);
            float4 b  = *reinterpret_cast<float4*>(&ws[k][tc * 4]);
            unsigned long long rp[4];
            rp[0] = pk2(a0.x, a0.y);
            rp[1] = pk2(a0.z, a0.w);
            rp[2] = pk2(a1.x, a1.y);
            rp[3] = pk2(a1.z, a1.w);
            unsigned long long bd[4];
            bd[0] = pk2(b.x, b.x);
            bd[1] = pk2(b.y, b.y);
            bd[2] = pk2(b.z, b.z);
            bd[3] = pk2(b.w, b.w);
#pragma unroll
            for (int p = 0; p < 4; ++p)
#pragma unroll
                for (int j = 0; j < 4; ++j)
                    acc2[p][j] = fma2(rp[p], bd[j], acc2[p][j]);
        }
        __syncthreads();
    }

#pragma unroll
    for (int p = 0; p < 4; ++p) {
        float lo[4], hi[4];
#pragma unroll
        for (int j = 0; j < 4; ++j) upk2(acc2[p][j], lo[j], hi[j]);
        int r0 = row0 + tr * 8 + 2 * p;
        if (r0 < N)
            *reinterpret_cast<float4*>(&g_h1[(size_t)r0 * HID + tc * 4]) =
                make_float4(lo[0], lo[1], lo[2], lo[3]);
        if (r0 + 1 < N)
            *reinterpret_cast<float4*>(&g_h1[(size_t)(r0 + 1) * HID + tc * 4]) =
                make_float4(hi[0], hi[1], hi[2], hi[3]);
    }
}

// ---------------- gather1: agg1[d] = dinv[d]^2*h1[d] + sum_e dinv[s]dinv[d]*h1[s] ----
__global__ void k_gather1(int N) {
    int t = blockIdx.x * blockDim.x + threadIdx.x;
    int node = t >> 4;
    if (node >= N) return;
    int c = (t & 15) * 4;

    float dd = g_dinv[node];
    float4 acc = *reinterpret_cast<const float4*>(&g_h1[(size_t)node * HID + c]);
    float w0 = dd * dd;
    acc.x *= w0; acc.y *= w0; acc.z *= w0; acc.w *= w0;

    int j   = g_offsets[node];
    int end = g_offsets[node + 1];

    for (; j + 1 < end; j += 2) {
        int s0 = g_csr_src[j];
        int s1 = g_csr_src[j + 1];
        float w_0 = g_dinv[s0] * dd;
        float w_1 = g_dinv[s1] * dd;
        float4 v0 = *reinterpret_cast<const float4*>(&g_h1[(size_t)s0 * HID + c]);
        float4 v1 = *reinterpret_cast<const float4*>(&g_h1[(size_t)s1 * HID + c]);
        acc.x += w_0 * v0.x + w_1 * v1.x;
        acc.y += w_0 * v0.y + w_1 * v1.y;
        acc.z += w_0 * v0.z + w_1 * v1.z;
        acc.w += w_0 * v0.w + w_1 * v1.w;
    }
    if (j < end) {
        int s = g_csr_src[j];
        float w = g_dinv[s] * dd;
        float4 v = *reinterpret_cast<const float4*>(&g_h1[(size_t)s * HID + c]);
        acc.x += w * v.x; acc.y += w * v.y;
        acc.z += w * v.z; acc.w += w * v.w;
    }
    *reinterpret_cast<float4*>(&g_agg1[(size_t)node * HID + c]) = acc;
}

// ---------------- GEMM2 (fused relu(agg1+b1)): h2 = relu(agg1+b1) @ W2 ----------------
__global__ void k_gemm2(const float* __restrict__ W2, const float* __restrict__ b1, int N) {
    __shared__ __align__(16) float ws[64][16];
    __shared__ float bs[64];
    for (int i = threadIdx.x; i < 64 * 16; i += blockDim.x)
        ws[i >> 4][i & 15] = W2[i];
    if (threadIdx.x < 64) bs[threadIdx.x] = b1[threadIdx.x];
    __syncthreads();

    int r = blockIdx.x * blockDim.x + threadIdx.x;
    if (r >= N) return;

    float4 acc[4];
#pragma unroll
    for (int j = 0; j < 4; ++j) acc[j] = make_float4(0.f, 0.f, 0.f, 0.f);

    const float4* xr = reinterpret_cast<const float4*>(g_agg1 + (size_t)r * HID);
#pragma unroll
    for (int k4 = 0; k4 < 16; ++k4) {
        float4 a = xr[k4];
        float aa[4];
        aa[0] = fmaxf(a.x + bs[k4 * 4 + 0], 0.f);
        aa[1] = fmaxf(a.y + bs[k4 * 4 + 1], 0.f);
        aa[2] = fmaxf(a.z + bs[k4 * 4 + 2], 0.f);
        aa[3] = fmaxf(a.w + bs[k4 * 4 + 3], 0.f);
#pragma unroll
        for (int u = 0; u < 4; ++u) {
            const float4* wr = reinterpret_cast<const float4*>(&ws[k4 * 4 + u][0]);
#pragma unroll
            for (int j = 0; j < 4; ++j) {
                float4 w = wr[j];
                acc[j].x += aa[u] * w.x;
                acc[j].y += aa[u] * w.y;
                acc[j].z += aa[u] * w.z;
                acc[j].w += aa[u] * w.w;
            }
        }
    }
    float4* o = reinterpret_cast<float4*>(g_h2 + (size_t)r * NOUT);
#pragma unroll
    for (int j = 0; j < 4; ++j) o[j] = acc[j];
}

// ---------------- gather2 + bias + log_softmax fused (4 thr/node) ----------------
__global__ void k_gather2final(float* __restrict__ out, const float* __restrict__ b2, int N) {
    int t = blockIdx.x * blockDim.x + threadIdx.x;
    int node = t >> 2;
    if (node >= N) return;
    int c = (t & 3) * 4;

    float dd = g_dinv[node];
    float4 acc = *reinterpret_cast<const float4*>(&g_h2[(size_t)node * NOUT + c]);
    float w0 = dd * dd;
    acc.x *= w0; acc.y *= w0; acc.z *= w0; acc.w *= w0;

    int j   = g_offsets[node];
    int end = g_offsets[node + 1];

    for (; j + 1 < end; j += 2) {
        int s0 = g_csr_src[j];
        int s1 = g_csr_src[j + 1];
        float w_0 = g_dinv[s0] * dd;
        float w_1 = g_dinv[s1] * dd;
        float4 v0 = *reinterpret_cast<const float4*>(&g_h2[(size_t)s0 * NOUT + c]);
        float4 v1 = *reinterpret_cast<const float4*>(&g_h2[(size_t)s1 * NOUT + c]);
        acc.x += w_0 * v0.x + w_1 * v1.x;
        acc.y += w_0 * v0.y + w_1 * v1.y;
        acc.z += w_0 * v0.z + w_1 * v1.z;
        acc.w += w_0 * v0.w + w_1 * v1.w;
    }
    if (j < end) {
        int s = g_csr_src[j];
        float w = g_dinv[s] * dd;
        float4 v = *reinterpret_cast<const float4*>(&g_h2[(size_t)s * NOUT + c]);
        acc.x += w * v.x; acc.y += w * v.y;
        acc.z += w * v.z; acc.w += w * v.w;
    }

    // bias
    acc.x += b2[c + 0]; acc.y += b2[c + 1];
    acc.z += b2[c + 2]; acc.w += b2[c + 3];

    // log_softmax over the node's 16 values, spread across 4 consecutive lanes
    float m = fmaxf(fmaxf(acc.x, acc.y), fmaxf(acc.z, acc.w));
    m = fmaxf(m, __shfl_xor_sync(0xffffffffu, m, 1));
    m = fmaxf(m, __shfl_xor_sync(0xffffffffu, m, 2));
    float s = __expf(acc.x - m) + __expf(acc.y - m) +
              __expf(acc.z - m) + __expf(acc.w - m);
    s += __shfl_xor_sync(0xffffffffu, s, 1);
    s += __shfl_xor_sync(0xffffffffu, s, 2);
    float l = m + __logf(s);

    float4 r = make_float4(acc.x - l, acc.y - l, acc.z - l, acc.w - l);
    *reinterpret_cast<float4*>(&out[(size_t)node * NOUT + c]) = r;
}

extern "C" void kernel_launch(void* const* d_in, const int* in_sizes, int n_in,
                              void* d_out, int out_size) {
    const float* x  = nullptr;  const void* ei = nullptr;
    const float* W1 = nullptr;  const float* b1 = nullptr;
    const float* W2 = nullptr;  const float* b2 = nullptr;
    int n_x = 0, n_e = 0;
    for (int i = 0; i < n_in; ++i) {
        int s = in_sizes[i];
        if      (s == 16)            b2 = (const float*)d_in[i];
        else if (s == 64)            b1 = (const float*)d_in[i];
        else if (s == 1024)          W2 = (const float*)d_in[i];
        else if (s == 256 * 64)      W1 = (const float*)d_in[i];
        else if (s == 3200000)     { ei = d_in[i]; n_e = s; }
        else                       { x = (const float*)d_in[i]; n_x = s; }
    }
    const int N = n_x / IN_K;
    const int E = n_e / 2;
    float* out = (float*)d_out;
    const int NB = (N + SCAN_BS - 1) / SCAN_BS;

    k_prep   <<<(N + 255) / 256, 256>>>((const int*)ei, N);       // 1
    k_count  <<<(E + 255) / 256, 256>>>(ei, E);                   // 2
    k_scan1  <<<NB, SCAN_BS>>>(N);                                // 3
    k_gemm1  <<<(N + 127) / 128, 256>>>(x, W1, N);                // 4 (profiled)
    k_scan2  <<<1, 32>>>(NB, N);                                  // 5
    k_scan3r <<<(N + 255) / 256, 256>>>(N);                       // 6
    k_fill   <<<(E + 255) / 256, 256>>>(ei, E);                   // 7
    k_gather1<<<(N * 16 + 255) / 256, 256>>>(N);                  // 8
    k_gemm2  <<<(N + 255) / 256, 256>>>(W2, b1, N);               // 9
    k_gather2final<<<(N * 4 + 255) / 256, 256>>>(out, b2, N);     // 10
}